// round 15
// baseline (speedup 1.0000x reference)
#include <cuda_runtime.h>
#include <cuda_fp16.h>
#include <cstdint>

#define B_   2
#define S_   2048
#define H_   16
#define HKV_ 8
#define D_   128
#define NROW (B_*S_)

// Scratch (device globals)
__device__ __align__(16) __half g_hs16[(size_t)NROW*2048];
__device__ __align__(16) __half g_w16 [(size_t)2048*2048];
__device__ __align__(16) __half g_wo16[(size_t)2048*2048];
__device__ __align__(16) __half g_A   [(size_t)NROW*2048];
__device__ __align__(16) __half g_q   [(size_t)B_*H_  *S_*D_]; // scaled by log2e/sqrt(D)
__device__ __align__(16) __half g_k   [(size_t)B_*HKV_*S_*D_];
__device__ __align__(16) __half g_v   [(size_t)B_*HKV_*S_*D_]; // d-MAJOR: [(b,kv)][d][s/2] u32 k-pairs
__device__ __align__(16) __half g_ao16[(size_t)NROW*2048];

__device__ __forceinline__ uint32_t h2rn(float a, float b) {
    __half2 h = __floats2half2_rn(a, b);
    return *reinterpret_cast<uint32_t*>(&h);
}
__device__ __forceinline__ float ex2(float x) {
    float r; asm("ex2.approx.f32 %0, %1;" : "=f"(r) : "f"(x)); return r;
}
__device__ __forceinline__ uint32_t hex2(float a, float b) {
    __half2 h = h2exp2(__floats2half2_rn(a, b));
    return *reinterpret_cast<uint32_t*>(&h);
}
__device__ __forceinline__ void mma_f16(float* c, const uint32_t* a, const uint32_t* b) {
    asm volatile(
        "mma.sync.aligned.m16n8k16.row.col.f32.f16.f16.f32 "
        "{%0,%1,%2,%3}, {%4,%5,%6,%7}, {%8,%9}, {%0,%1,%2,%3};"
        : "+f"(c[0]), "+f"(c[1]), "+f"(c[2]), "+f"(c[3])
        : "r"(a[0]), "r"(a[1]), "r"(a[2]), "r"(a[3]), "r"(b[0]), "r"(b[1]));
}
__device__ __forceinline__ void ldsm4(uint32_t* r, uint32_t addr) {
    asm volatile("ldmatrix.sync.aligned.m8n8.x4.shared.b16 {%0,%1,%2,%3}, [%4];"
        : "=r"(r[0]), "=r"(r[1]), "=r"(r[2]), "=r"(r[3]) : "r"(addr));
}
__device__ __forceinline__ uint32_t smem_u32(const void* p) {
    uint32_t a;
    asm("{ .reg .u64 t; cvta.to.shared.u64 t, %1; cvt.u32.u64 %0, t; }" : "=r"(a) : "l"(p));
    return a;
}
__device__ __forceinline__ void cp16(uint32_t d, const void* s) {
    asm volatile("cp.async.cg.shared.global [%0], [%1], 16;" :: "r"(d), "l"(s));
}
#define CP_COMMIT() asm volatile("cp.async.commit_group;")

// ---------------------------------------------------------------------------
// fused fp32 -> fp16 conversion of all 5 inputs
// ---------------------------------------------------------------------------
__global__ void __launch_bounds__(256) cvt_all(
    const float* __restrict__ hs, const float* __restrict__ waq,
    const float* __restrict__ wak, const float* __restrict__ wav,
    const float* __restrict__ wo)
{
    size_t g = (size_t)blockIdx.x * 256 + threadIdx.x;
    const float* s; __half* d;
    if (g < 1048576)      { s = hs;  d = g_hs16; }
    else if (g < 1310720) { g -= 1048576; s = waq; d = g_w16; }
    else if (g < 1441792) { g -= 1310720; s = wak; d = g_w16 + (size_t)1024*2048; }
    else if (g < 1572864) { g -= 1441792; s = wav; d = g_w16 + (size_t)1536*2048; }
    else                  { g -= 1572864; s = wo;  d = g_wo16; }
    size_t i = g * 8;
    float4 a = *(const float4*)(s + i);
    float4 b = *(const float4*)(s + i + 4);
    uint4 o = { h2rn(a.x,a.y), h2rn(a.z,a.w), h2rn(b.x,b.y), h2rn(b.z,b.w) };
    *(uint4*)(d + i) = o;
}

// ---------------------------------------------------------------------------
// fp16 GEMM: 128 thr, 4 warps (2x2), warp tile 64x64, K-chunks of 64,
// 3-stage cp.async pipeline, single sync per chunk, 2 CTAs/SM.
// ---------------------------------------------------------------------------
#define GTS 72
#define GSTG (128*GTS)
#define G16_SMEM (3*2*GSTG*2)   // 110592 B (x2 CTAs = 221184 <= 228KB/SM)

__device__ __forceinline__ void g16_issue(uint32_t sb, int stg,
    const __half* __restrict__ A, const __half* __restrict__ B, int tid)
{
    uint32_t ab = sb + stg * 2 * GSTG * 2;
    uint32_t bb = ab + GSTG * 2;
    #pragma unroll
    for (int i = 0; i < 8; i++) {
        int idx = tid + (i << 7);
        int row = idx >> 3, seg = idx & 7;
        cp16(ab + row * 144 + seg * 16, A + (size_t)row * 2048 + seg * 8);
        cp16(bb + row * 144 + seg * 16, B + (size_t)row * 2048 + seg * 8);
    }
}

__device__ __forceinline__ void gemm16_acc(
    uint32_t sb, const __half* __restrict__ A,
    const __half* __restrict__ B, float acc[4][8][4])
{
    const int tid = threadIdx.x, wid = tid >> 5, lane = tid & 31;
    const int wm = wid >> 1, wn = wid & 1;
    const int arow = (lane & 7) + ((lane >> 3) & 1) * 8, acol = (lane >> 4) * 8;
    const int brow = (lane & 7) + (lane >> 4) * 8,       bcol = ((lane >> 3) & 1) * 8;

    #pragma unroll
    for (int s = 0; s < 2; s++) {
        g16_issue(sb, s, A + s * 64, B + s * 64, tid);
        CP_COMMIT();
    }

    for (int c = 0; c < 32; c++) {
        if (c + 2 < 32) asm volatile("cp.async.wait_group 1;");
        else            asm volatile("cp.async.wait_group 0;");
        __syncthreads();
        if (c + 2 < 32) {
            g16_issue(sb, (c + 2) % 3, A + (c + 2) * 64, B + (c + 2) * 64, tid);
            CP_COMMIT();
        }

        uint32_t ab = sb + (c % 3) * 2 * GSTG * 2;
        uint32_t bb = ab + GSTG * 2;
        #pragma unroll
        for (int ks = 0; ks < 4; ks++) {
            uint32_t af[4][4], bfr[4][4];
            #pragma unroll
            for (int mi = 0; mi < 4; mi++)
                ldsm4(af[mi], ab + ((wm*64 + mi*16 + arow) * GTS + ks*16 + acol) * 2);
            #pragma unroll
            for (int ni = 0; ni < 4; ni++)
                ldsm4(bfr[ni], bb + ((wn*64 + ni*16 + brow) * GTS + ks*16 + bcol) * 2);
            #pragma unroll
            for (int mi = 0; mi < 4; mi++)
                #pragma unroll
                for (int ni = 0; ni < 4; ni++) {
                    mma_f16(acc[mi][ni*2],   af[mi], bfr[ni]);
                    mma_f16(acc[mi][ni*2+1], af[mi], bfr[ni] + 2);
                }
        }
    }
}

// merged 3-way projection -> g_A (fp16, /64 folded)
__global__ void __launch_bounds__(128, 2) proj_h()
{
    extern __shared__ __half smh[];
    const int x = blockIdx.x;
    const size_t m0 = (size_t)blockIdx.y << 7;

    float acc[4][8][4];
    #pragma unroll
    for (int i = 0; i < 4; i++)
        #pragma unroll
        for (int j = 0; j < 8; j++)
            #pragma unroll
            for (int r = 0; r < 4; r++) acc[i][j][r] = 0.f;

    gemm16_acc(smem_u32(smh), g_hs16 + m0 * 2048, g_w16 + (size_t)x * 128 * 2048, acc);

    const int tid = threadIdx.x, wid = tid >> 5, lane = tid & 31;
    const int wm = wid >> 1, wn = wid & 1, lr = lane >> 2, lc = lane & 3;
    const float al = 1.0f / 64.0f;
    __half* C = g_A + m0 * 2048 + x * 128;
    #pragma unroll
    for (int mi = 0; mi < 4; mi++) {
        const int row = wm * 64 + mi * 16 + lr;
        #pragma unroll
        for (int nj = 0; nj < 8; nj++) {
            const int col = wn * 64 + nj * 8 + lc * 2;
            *(uint32_t*)(C + (size_t)row * 2048 + col)     = h2rn(acc[mi][nj][0]*al, acc[mi][nj][1]*al);
            *(uint32_t*)(C + (size_t)(row+8) * 2048 + col) = h2rn(acc[mi][nj][2]*al, acc[mi][nj][3]*al);
        }
    }
}

// output projection
__global__ void __launch_bounds__(128, 2) oproj_h(float* __restrict__ out)
{
    extern __shared__ __half smh[];
    const size_t m0 = (size_t)blockIdx.y << 7;
    const size_t n0 = (size_t)blockIdx.x << 7;

    float acc[4][8][4];
    #pragma unroll
    for (int i = 0; i < 4; i++)
        #pragma unroll
        for (int j = 0; j < 8; j++)
            #pragma unroll
            for (int r = 0; r < 4; r++) acc[i][j][r] = 0.f;

    gemm16_acc(smem_u32(smh), g_ao16 + m0 * 2048, g_wo16 + n0 * 2048, acc);

    const int tid = threadIdx.x, wid = tid >> 5, lane = tid & 31;
    const int wm = wid >> 1, wn = wid & 1, lr = lane >> 2, lc = lane & 3;
    float* C = out + m0 * 2048 + n0;
    #pragma unroll
    for (int mi = 0; mi < 4; mi++) {
        const int row = wm * 64 + mi * 16 + lr;
        #pragma unroll
        for (int nj = 0; nj < 8; nj++) {
            const int col = wn * 64 + nj * 8 + lc * 2;
            float2 v0 = { acc[mi][nj][0], acc[mi][nj][1] };
            float2 v1 = { acc[mi][nj][2], acc[mi][nj][3] };
            *(float2*)(C + (size_t)row * 2048 + col)     = v0;
            *(float2*)(C + (size_t)(row+8) * 2048 + col) = v1;
        }
    }
}

// ---------------------------------------------------------------------------
// q/k/v build (fp16 mma, K=64) + RoPE + scatter. grid (32,32).
// V written d-major packed via register transpose (shfl + byte_perm).
// ---------------------------------------------------------------------------
#define QATS 72
#define BPS  136
#define QKV_SMEM (128*QATS*2 + 32*BPS*4)
#define SC2_ 0.12752450221065472f   // (1/sqrt(128)) * log2(e)

__global__ void __launch_bounds__(256, 1) qkv_h(
    const float* __restrict__ Bq, const float* __restrict__ Bk, const float* __restrict__ Bv,
    const float* __restrict__ fcos, const float* __restrict__ fsin,
    const int* __restrict__ widx)
{
    extern __shared__ __align__(16) char smraw[];
    __half*   As = (__half*)smraw;
    uint32_t* Bp = (uint32_t*)(smraw + 128*QATS*2);

    const int tid = threadIdx.x, w = tid >> 5, lane = tid & 31;
    const int lr = lane >> 2, lc = lane & 3;
    const int m0 = blockIdx.x << 7;
    const int hh = blockIdx.y;

    const float* Bmat; int aoff;
    if (hh < 16)      { Bmat = Bq + (size_t)hh * 8192;        aoff = hh * 64; }
    else if (hh < 24) { Bmat = Bk + (size_t)(hh - 16) * 8192; aoff = 1024 + (hh - 16) * 64; }
    else              { Bmat = Bv + (size_t)(hh - 24) * 8192; aoff = 1536 + (hh - 24) * 64; }

    #pragma unroll
    for (int i = 0; i < 4; i++) {
        int idx = tid + (i << 8);
        int r = idx >> 3, g = idx & 7;
        *(uint4*)(As + r * QATS + g * 8) =
            *(const uint4*)(g_A + (size_t)(m0 + r) * 2048 + aoff + g * 8);
    }
    #pragma unroll
    for (int i = 0; i < 4; i++) {
        int idx = tid + (i << 8);
        int r2 = idx >> 5, cg = idx & 31;
        float4 a = *(const float4*)(Bmat + (size_t)(2*r2) * 128 + cg * 4);
        float4 b = *(const float4*)(Bmat + (size_t)(2*r2+1) * 128 + cg * 4);
        uint4 o = { h2rn(a.x,b.x), h2rn(a.y,b.y), h2rn(a.z,b.z), h2rn(a.w,b.w) };
        *(uint4*)(Bp + r2 * BPS + cg * 4) = o;
    }
    __syncthreads();

    float acc[16][4];
    #pragma unroll
    for (int i = 0; i < 16; i++)
        #pragma unroll
        for (int j = 0; j < 4; j++) acc[i][j] = 0.f;

    #pragma unroll
    for (int s = 0; s < 4; s++) {
        const __half* pa = As + (w * 16 + lr) * QATS + s * 16 + 2 * lc;
        uint32_t af[4] = { *(const uint32_t*)(pa), *(const uint32_t*)(pa + 8*QATS),
                           *(const uint32_t*)(pa + 8), *(const uint32_t*)(pa + 8*QATS + 8) };
        #pragma unroll
        for (int nd = 0; nd < 16; nd++) {
            const uint32_t* pb = Bp + (s * 8 + lc) * BPS + nd * 8 + lr;
            uint32_t bf[2] = { pb[0], pb[4 * BPS] };
            mma_f16(acc[nd], af, bf);
        }
    }

    const int r0 = m0 + w * 16 + lr, r1 = r0 + 8;
    const int b  = r0 >> 11;
    const int s0 = r0 & 2047, s1 = s0 + 8;

    if (hh < 16) {
        #pragma unroll
        for (int i = 0; i < 16; i++)
            #pragma unroll
            for (int j = 0; j < 4; j++) acc[i][j] *= SC2_;
        __half* o0 = g_q + ((size_t)(b * H_ + hh) * S_ + s0) * D_;
        __half* o1 = g_q + ((size_t)(b * H_ + hh) * S_ + s1) * D_;
        #pragma unroll
        for (int nd = 0; nd < 8; nd++) {
            const int d0 = (nd << 3) + 2 * lc;
            float2 c0 = *(const float2*)(fcos + (size_t)s0*64 + d0);
            float2 z0 = *(const float2*)(fsin + (size_t)s0*64 + d0);
            float2 c1 = *(const float2*)(fcos + (size_t)s1*64 + d0);
            float2 z1 = *(const float2*)(fsin + (size_t)s1*64 + d0);
            *(uint32_t*)(o0+d0)    = h2rn(acc[nd][0]*c0.x - acc[nd+8][0]*z0.x,
                                          acc[nd][1]*c0.y - acc[nd+8][1]*z0.y);
            *(uint32_t*)(o0+d0+64) = h2rn(acc[nd][0]*z0.x + acc[nd+8][0]*c0.x,
                                          acc[nd][1]*z0.y + acc[nd+8][1]*c0.y);
            *(uint32_t*)(o1+d0)    = h2rn(acc[nd][2]*c1.x - acc[nd+8][2]*z1.x,
                                          acc[nd][3]*c1.y - acc[nd+8][3]*z1.y);
            *(uint32_t*)(o1+d0+64) = h2rn(acc[nd][2]*z1.x + acc[nd+8][2]*c1.x,
                                          acc[nd][3]*z1.y + acc[nd+8][3]*c1.y);
        }
    } else if (hh < 24) {
        int p0 = widx[s0], p1 = widx[s1];
        __half* o0 = g_k + ((size_t)(b * HKV_ + hh-16) * S_ + p0) * D_;
        __half* o1 = g_k + ((size_t)(b * HKV_ + hh-16) * S_ + p1) * D_;
        #pragma unroll
        for (int nd = 0; nd < 8; nd++) {
            const int d0 = (nd << 3) + 2 * lc;
            float2 c0 = *(const float2*)(fcos + (size_t)p0*64 + d0);
            float2 z0 = *(const float2*)(fsin + (size_t)p0*64 + d0);
            float2 c1 = *(const float2*)(fcos + (size_t)p1*64 + d0);
            float2 z1 = *(const float2*)(fsin + (size_t)p1*64 + d0);
            *(uint32_t*)(o0+d0)    = h2rn(acc[nd][0]*c0.x - acc[nd+8][0]*z0.x,
                                          acc[nd][1]*c0.y - acc[nd+8][1]*z0.y);
            *(uint32_t*)(o0+d0+64) = h2rn(acc[nd][0]*z0.x + acc[nd+8][0]*c0.x,
                                          acc[nd][1]*z0.y + acc[nd+8][1]*c0.y);
            *(uint32_t*)(o1+d0)    = h2rn(acc[nd][2]*c1.x - acc[nd+8][2]*z1.x,
                                          acc[nd][3]*c1.y - acc[nd+8][3]*z1.y);
            *(uint32_t*)(o1+d0+64) = h2rn(acc[nd][2]*z1.x + acc[nd+8][2]*c1.x,
                                          acc[nd][3]*z1.y + acc[nd+8][3]*c1.y);
        }
    } else {   // V: register transpose -> d-major packed g_v
        const int par = lr & 1;
        int pe0 = widx[s0 - par] >> 1;
        int pe1 = widx[s0 - par + 8] >> 1;
        uint32_t* gvt = (uint32_t*)g_v + (size_t)(b * HKV_ + hh - 24) * (D_ * (S_/2));
        #pragma unroll
        for (int nd = 0; nd < 16; nd++) {
            uint32_t v0 = h2rn(acc[nd][0], acc[nd][1]);
            uint32_t v1 = h2rn(acc[nd][2], acc[nd][3]);
            uint32_t q0 = __shfl_xor_sync(0xffffffffu, v0, 4);
            uint32_t q1 = __shfl_xor_sync(0xffffffffu, v1, 4);
            uint32_t o0 = par ? __byte_perm(v0, q0, 0x3276) : __byte_perm(v0, q0, 0x5410);
            uint32_t o1 = par ? __byte_perm(v1, q1, 0x3276) : __byte_perm(v1, q1, 0x5410);
            const int d = (nd << 3) + 2 * lc + par;
            gvt[(size_t)d * (S_/2) + pe0] = o0;
            gvt[(size_t)d * (S_/2) + pe1] = o1;
        }
    }
}

// ---------------------------------------------------------------------------
// Flash attention: 128x128 tiles, fp16 mma, cp.async double buffer,
// d-major V (ldsm4 PV frags), tensor-core row sums, f16x2 exp.
// ---------------------------------------------------------------------------
#define KTS 136
#define VTS 68
#define FL_BUF 71808
#define FL_SMEM (2*FL_BUF)

__device__ __forceinline__ void fl_issue(uint32_t sb, int buf,
    const __half* __restrict__ kp, const uint32_t* __restrict__ vt, int kt, int tid)
{
    uint32_t kb = sb + buf * FL_BUF;
    uint32_t vb = kb + 34816u;
    #pragma unroll
    for (int i = 0; i < 8; i++) {
        int idx = tid + (i << 8);
        int r = idx >> 4, g = idx & 15;
        cp16(kb + (r * KTS + g * 8) * 2, kp + (size_t)r * 128 + g * 8);
    }
    #pragma unroll
    for (int i = 0; i < 8; i++) {
        int idx = tid + (i << 8);
        int d = idx >> 4, g = idx & 15;
        cp16(vb + (d * VTS + g * 4) * 4, vt + (size_t)d * (S_/2) + kt * 64 + g * 4);
    }
}

__global__ void __launch_bounds__(256, 1) flash_h()
{
    extern __shared__ __align__(16) char smraw[];
    const uint32_t sb = smem_u32(smraw);

    const int tid = threadIdx.x, w = tid >> 5, lane = tid & 31;
    const int lr = lane >> 2, lc = lane & 3;
    const int arow = (lane & 7) + ((lane >> 3) & 1) * 8, acol = (lane >> 4) * 8;
    const int brow = (lane & 7) + (lane >> 4) * 8,       bcol = ((lane >> 3) & 1) * 8;
    const int vrow = ((lane >> 4) << 3) + (lane & 7),    vc4  = ((lane >> 3) & 1) * 4;
    const int qt = (int)gridDim.x - 1 - (int)blockIdx.x;
    const int bh = blockIdx.y;
    const int b = bh >> 4, h = bh & 15, kvh = h >> 1;
    const int qp = qt << 7;

    const __half*   qbase = g_q + ((size_t)(b * H_ + h) * S_ + qp) * D_;
    const __half*   kbase = g_k + (size_t)(b * HKV_ + kvh) * S_ * D_;
    const uint32_t* vtb_g = (const uint32_t*)g_v + (size_t)(b * HKV_ + kvh) * (D_ * (S_/2));

    __half* Qst = (__half*)smraw;
    #pragma unroll
    for (int i = 0; i < 8; i++) {
        int idx = tid + (i << 8);
        int r = idx >> 4, g = idx & 15;
        *(uint4*)(Qst + r * KTS + g * 8) = *(const uint4*)(qbase + (size_t)r * 128 + g * 8);
    }
    __syncthreads();
    uint32_t qf[8][4];
    #pragma unroll
    for (int k8 = 0; k8 < 8; k8++)
        ldsm4(qf[k8], sb + ((w * 16 + arow) * KTS + (k8 << 4) + acol) * 2);

    {
        uint32_t* v0 = (uint32_t*)(smraw + 34816);
        uint32_t* v1 = (uint32_t*)(smraw + FL_BUF + 34816);
        for (int i = tid; i < 512; i += 256) {
            int r = i >> 6, c = i & 63;
            v0[(128 + r) * VTS + c] = 0x3C003C00u;
            v1[(128 + r) * VTS + c] = 0x3C003C00u;
        }
    }
    __syncthreads();

    float oacc[17][4];
    #pragma unroll
    for (int i = 0; i < 17; i++)
        #pragma unroll
        for (int j = 0; j < 4; j++) oacc[i][j] = 0.f;
    float m0 = -1e30f, m1 = -1e30f;
    const int r0g = qp + w * 16 + lr, r1g = r0g + 8;

    fl_issue(sb, 0, kbase, vtb_g, 0, tid);
    CP_COMMIT();

    for (int kt = 0; kt <= qt; kt++) {
        asm volatile("cp.async.wait_group 0;");
        __syncthreads();
        if (kt < qt) {
            fl_issue(sb, (kt + 1) & 1, kbase + (size_t)(kt + 1) * 16384,
                     vtb_g, kt + 1, tid);
            CP_COMMIT();
        }

        const uint32_t kb  = sb + (kt & 1) * FL_BUF;
        const uint32_t vtb = kb + 34816u;
        const uint32_t* Vt = (const uint32_t*)(smraw + (kt & 1) * FL_BUF + 34816);

        float sacc[16][4];
        #pragma unroll
        for (int i = 0; i < 16; i++)
            #pragma unroll
            for (int j = 0; j < 4; j++) sacc[i][j] = 0.f;
        #pragma unroll
        for (int k8 = 0; k8 < 8; k8++) {
            #pragma unroll
            for (int ntp = 0; ntp < 8; ntp++) {
                uint32_t bq[4];
                ldsm4(bq, kb + ((ntp * 16 + brow) * KTS + (k8 << 4) + bcol) * 2);
                mma_f16(sacc[2*ntp],     qf[k8], bq);
                mma_f16(sacc[2*ntp + 1], qf[k8], bq + 2);
            }
        }

        if (kt == qt) {
            const int cb = kt << 7;
            #pragma unroll
            for (int nt = 0; nt < 16; nt++) {
                int c0 = cb + nt * 8 + 2 * lc;
                if (c0     > r0g) sacc[nt][0] = -1e30f;
                if (c0 + 1 > r0g) sacc[nt][1] = -1e30f;
                if (c0     > r1g) sacc[nt][2] = -1e30f;
                if (c0 + 1 > r1g) sacc[nt][3] = -1e30f;
            }
        }

        float mi0 = -1e30f, mi1 = -1e30f;
        #pragma unroll
        for (int nt = 0; nt < 16; nt++) {
            mi0 = fmaxf(mi0, fmaxf(sacc[nt][0], sacc[nt][1]));
            mi1 = fmaxf(mi1, fmaxf(sacc[nt][2], sacc[nt][3]));
        }
        mi0 = fmaxf(mi0, __shfl_xor_sync(0xffffffffu, mi0, 1));
        mi0 = fmaxf(mi0, __shfl_xor_sync(0xffffffffu, mi0, 2));
        mi1 = fmaxf(mi1, __shfl_xor_sync(0xffffffffu, mi1, 1));
        mi1 = fmaxf(mi1, __shfl_xor_sync(0xffffffffu, mi1, 2));
        float mn0 = fmaxf(m0, mi0), mn1 = fmaxf(m1, mi1);
        float sf0 = ex2(m0 - mn0), sf1 = ex2(m1 - mn1);
        m0 = mn0; m1 = mn1;

        uint32_t pf[16][2];
        #pragma unroll
        for (int nt = 0; nt < 16; nt++) {
            pf[nt][0] = hex2(sacc[nt][0] - m0, sacc[nt][1] - m0);
            pf[nt][1] = hex2(sacc[nt][2] - m1, sacc[nt][3] - m1);
        }

        #pragma unroll
        for (int nd = 0; nd < 17; nd++) {
            oacc[nd][0] *= sf0; oacc[nd][1] *= sf0;
            oacc[nd][2] *= sf1; oacc[nd][3] *= sf1;
        }

        #pragma unroll
        for (int ks = 0; ks < 8; ks++) {
            uint32_t af[4] = { pf[2*ks][0], pf[2*ks][1], pf[2*ks+1][0], pf[2*ks+1][1] };
            #pragma unroll
            for (int ndp = 0; ndp < 8; ndp++) {
                uint32_t bv[4];
                ldsm4(bv, vtb + ((ndp * 16 + vrow) * VTS + ks * 8 + vc4) * 4);
                mma_f16(oacc[2*ndp],     af, bv);
                mma_f16(oacc[2*ndp + 1], af, bv + 2);
            }
            const uint32_t* po = Vt + (128 + lr) * VTS + ks * 8 + lc;
            uint32_t bo[2] = { po[0], po[4] };
            mma_f16(oacc[16], af, bo);
        }
        __syncthreads();
    }

    float i0 = 1.f / oacc[16][0], i1 = 1.f / oacc[16][2];
    __half* o0 = g_ao16 + ((size_t)b * S_ + r0g) * 2048 + h * 128 + 2 * lc;
    __half* o1 = g_ao16 + ((size_t)b * S_ + r1g) * 2048 + h * 128 + 2 * lc;
    #pragma unroll
    for (int nd = 0; nd < 16; nd++) {
        *(uint32_t*)(o0 + nd * 8) = h2rn(oacc[nd][0] * i0, oacc[nd][1] * i0);
        *(uint32_t*)(o1 + nd * 8) = h2rn(oacc[nd][2] * i1, oacc[nd][3] * i1);
    }
}

// ---------------------------------------------------------------------------
extern "C" void kernel_launch(void* const* d_in, const int* in_sizes, int n_in,
                              void* d_out, int out_size)
{
    const float* hs   = (const float*)d_in[0];
    const float* WAq  = (const float*)d_in[1];
    const float* WAk  = (const float*)d_in[2];
    const float* WAv  = (const float*)d_in[3];
    const float* Bq   = (const float*)d_in[4];
    const float* Bk   = (const float*)d_in[5];
    const float* Bv   = (const float*)d_in[6];
    const float* Wo   = (const float*)d_in[7];
    const float* fcos = (const float*)d_in[8];
    const float* fsin = (const float*)d_in[9];
    const int*   widx = (const int*)d_in[11];
    float* out = (float*)d_out;

    cudaFuncSetAttribute(proj_h,  cudaFuncAttributeMaxDynamicSharedMemorySize, G16_SMEM);
    cudaFuncSetAttribute(oproj_h, cudaFuncAttributeMaxDynamicSharedMemorySize, G16_SMEM);
    cudaFuncSetAttribute(qkv_h,   cudaFuncAttributeMaxDynamicSharedMemorySize, QKV_SMEM);
    cudaFuncSetAttribute(flash_h, cudaFuncAttributeMaxDynamicSharedMemorySize, FL_SMEM);

    cvt_all<<<8192, 256>>>(hs, WAq, WAk, WAv, Wo);
    proj_h <<<dim3(16, 32), 128, G16_SMEM>>>();
    qkv_h  <<<dim3(32, 32), 256, QKV_SMEM>>>(Bq, Bk, Bv, fcos, fsin, widx);
    flash_h<<<dim3(S_ / 128, B_ * H_), 256, FL_SMEM>>>();
    oproj_h<<<dim3(16, 32), 128, G16_SMEM>>>(out);
}

// round 16
// speedup vs baseline: 1.0097x; 1.0097x over previous
#include <cuda_runtime.h>
#include <cuda_fp16.h>
#include <cstdint>

#define B_   2
#define S_   2048
#define H_   16
#define HKV_ 8
#define D_   128
#define NROW (B_*S_)

// Scratch (device globals)
__device__ __align__(16) __half g_hs16[(size_t)NROW*2048];
__device__ __align__(16) __half g_w16 [(size_t)2048*2048];
__device__ __align__(16) __half g_wo16[(size_t)2048*2048];
__device__ __align__(16) __half g_A   [(size_t)NROW*2048];
__device__ __align__(16) __half g_q   [(size_t)B_*H_  *S_*D_]; // scaled by log2e/sqrt(D)
__device__ __align__(16) __half g_k   [(size_t)B_*HKV_*S_*D_];
__device__ __align__(16) __half g_v   [(size_t)B_*HKV_*S_*D_]; // d-MAJOR: [(b,kv)][d][s/2] u32 k-pairs
__device__ __align__(16) __half g_ao16[(size_t)NROW*2048];

__device__ __forceinline__ uint32_t h2rn(float a, float b) {
    __half2 h = __floats2half2_rn(a, b);
    return *reinterpret_cast<uint32_t*>(&h);
}
__device__ __forceinline__ float ex2(float x) {
    float r; asm("ex2.approx.f32 %0, %1;" : "=f"(r) : "f"(x)); return r;
}
__device__ __forceinline__ uint32_t hex2(float a, float b) {
    __half2 h = h2exp2(__floats2half2_rn(a, b));
    return *reinterpret_cast<uint32_t*>(&h);
}
__device__ __forceinline__ void mma_f16(float* c, const uint32_t* a, const uint32_t* b) {
    asm volatile(
        "mma.sync.aligned.m16n8k16.row.col.f32.f16.f16.f32 "
        "{%0,%1,%2,%3}, {%4,%5,%6,%7}, {%8,%9}, {%0,%1,%2,%3};"
        : "+f"(c[0]), "+f"(c[1]), "+f"(c[2]), "+f"(c[3])
        : "r"(a[0]), "r"(a[1]), "r"(a[2]), "r"(a[3]), "r"(b[0]), "r"(b[1]));
}
__device__ __forceinline__ void ldsm4(uint32_t* r, uint32_t addr) {
    asm volatile("ldmatrix.sync.aligned.m8n8.x4.shared.b16 {%0,%1,%2,%3}, [%4];"
        : "=r"(r[0]), "=r"(r[1]), "=r"(r[2]), "=r"(r[3]) : "r"(addr));
}
__device__ __forceinline__ uint32_t smem_u32(const void* p) {
    uint32_t a;
    asm("{ .reg .u64 t; cvta.to.shared.u64 t, %1; cvt.u32.u64 %0, t; }" : "=r"(a) : "l"(p));
    return a;
}
__device__ __forceinline__ void cp16(uint32_t d, const void* s) {
    asm volatile("cp.async.cg.shared.global [%0], [%1], 16;" :: "r"(d), "l"(s));
}
#define CP_COMMIT() asm volatile("cp.async.commit_group;")

// ---------------------------------------------------------------------------
// fused fp32 -> fp16 conversion of all 5 inputs
// ---------------------------------------------------------------------------
__global__ void __launch_bounds__(256) cvt_all(
    const float* __restrict__ hs, const float* __restrict__ waq,
    const float* __restrict__ wak, const float* __restrict__ wav,
    const float* __restrict__ wo)
{
    size_t g = (size_t)blockIdx.x * 256 + threadIdx.x;
    const float* s; __half* d;
    if (g < 1048576)      { s = hs;  d = g_hs16; }
    else if (g < 1310720) { g -= 1048576; s = waq; d = g_w16; }
    else if (g < 1441792) { g -= 1310720; s = wak; d = g_w16 + (size_t)1024*2048; }
    else if (g < 1572864) { g -= 1441792; s = wav; d = g_w16 + (size_t)1536*2048; }
    else                  { g -= 1572864; s = wo;  d = g_wo16; }
    size_t i = g * 8;
    float4 a = *(const float4*)(s + i);
    float4 b = *(const float4*)(s + i + 4);
    uint4 o = { h2rn(a.x,a.y), h2rn(a.z,a.w), h2rn(b.x,b.y), h2rn(b.z,b.w) };
    *(uint4*)(d + i) = o;
}

// ---------------------------------------------------------------------------
// fp16 GEMM: CTA tile 128x256, 256 thr, 8 warps (2x4, warp tile 64x64),
// K-chunks of 64, 3-stage cp.async pipeline, single sync per chunk.
// A staged once per chunk and reused across 4 B warp-columns (L2 traffic -25%).
// ---------------------------------------------------------------------------
#define GTS 72
#define A_ST_B (128*GTS*2)              // 18432 B
#define B_ST_B (256*GTS*2)              // 36864 B
#define STG_B  (A_ST_B + B_ST_B)        // 55296 B
#define G16_SMEM (3*STG_B)              // 165888 B

__device__ __forceinline__ void g16_issue(uint32_t sb, int stg,
    const __half* __restrict__ A, const __half* __restrict__ B, int tid)
{
    uint32_t ab = sb + stg * STG_B;
    uint32_t bb = ab + A_ST_B;
    #pragma unroll
    for (int i = 0; i < 4; i++) {       // A: 128 rows x 8 segs = 1024 tasks
        int idx = tid + (i << 8);
        int row = idx >> 3, seg = idx & 7;
        cp16(ab + row * 144 + seg * 16, A + (size_t)row * 2048 + seg * 8);
    }
    #pragma unroll
    for (int i = 0; i < 8; i++) {       // B: 256 rows x 8 segs = 2048 tasks
        int idx = tid + (i << 8);
        int row = idx >> 3, seg = idx & 7;
        cp16(bb + row * 144 + seg * 16, B + (size_t)row * 2048 + seg * 8);
    }
}

__device__ __forceinline__ void gemm16_acc(
    uint32_t sb, const __half* __restrict__ A,
    const __half* __restrict__ B, float acc[4][8][4])
{
    const int tid = threadIdx.x, wid = tid >> 5, lane = tid & 31;
    const int wm = wid >> 2, wn = wid & 3;
    const int arow = (lane & 7) + ((lane >> 3) & 1) * 8, acol = (lane >> 4) * 8;
    const int brow = (lane & 7) + (lane >> 4) * 8,       bcol = ((lane >> 3) & 1) * 8;

    #pragma unroll
    for (int s = 0; s < 2; s++) {
        g16_issue(sb, s, A + s * 64, B + s * 64, tid);
        CP_COMMIT();
    }

    for (int c = 0; c < 32; c++) {
        if (c + 2 < 32) asm volatile("cp.async.wait_group 1;");
        else            asm volatile("cp.async.wait_group 0;");
        __syncthreads();
        if (c + 2 < 32) {
            g16_issue(sb, (c + 2) % 3, A + (c + 2) * 64, B + (c + 2) * 64, tid);
            CP_COMMIT();
        }

        uint32_t ab = sb + (c % 3) * STG_B;
        uint32_t bb = ab + A_ST_B;
        #pragma unroll
        for (int ks = 0; ks < 4; ks++) {
            uint32_t af[4][4], bfr[4][4];
            #pragma unroll
            for (int mi = 0; mi < 4; mi++)
                ldsm4(af[mi], ab + ((wm*64 + mi*16 + arow) * GTS + ks*16 + acol) * 2);
            #pragma unroll
            for (int ni = 0; ni < 4; ni++)
                ldsm4(bfr[ni], bb + ((wn*64 + ni*16 + brow) * GTS + ks*16 + bcol) * 2);
            #pragma unroll
            for (int mi = 0; mi < 4; mi++)
                #pragma unroll
                for (int ni = 0; ni < 4; ni++) {
                    mma_f16(acc[mi][ni*2],   af[mi], bfr[ni]);
                    mma_f16(acc[mi][ni*2+1], af[mi], bfr[ni] + 2);
                }
        }
    }
}

// merged 3-way projection -> g_A (fp16, /64 folded); x spans 256 cols
__global__ void __launch_bounds__(256, 1) proj_h()
{
    extern __shared__ __half smh[];
    const int x = blockIdx.x;
    const size_t m0 = (size_t)blockIdx.y << 7;

    float acc[4][8][4];
    #pragma unroll
    for (int i = 0; i < 4; i++)
        #pragma unroll
        for (int j = 0; j < 8; j++)
            #pragma unroll
            for (int r = 0; r < 4; r++) acc[i][j][r] = 0.f;

    gemm16_acc(smem_u32(smh), g_hs16 + m0 * 2048, g_w16 + (size_t)x * 256 * 2048, acc);

    const int tid = threadIdx.x, wid = tid >> 5, lane = tid & 31;
    const int wm = wid >> 2, wn = wid & 3, lr = lane >> 2, lc = lane & 3;
    const float al = 1.0f / 64.0f;
    __half* C = g_A + m0 * 2048 + x * 256;
    #pragma unroll
    for (int mi = 0; mi < 4; mi++) {
        const int row = wm * 64 + mi * 16 + lr;
        #pragma unroll
        for (int nj = 0; nj < 8; nj++) {
            const int col = wn * 64 + nj * 8 + lc * 2;
            *(uint32_t*)(C + (size_t)row * 2048 + col)     = h2rn(acc[mi][nj][0]*al, acc[mi][nj][1]*al);
            *(uint32_t*)(C + (size_t)(row+8) * 2048 + col) = h2rn(acc[mi][nj][2]*al, acc[mi][nj][3]*al);
        }
    }
}

// output projection (CTA tile 128x256)
__global__ void __launch_bounds__(256, 1) oproj_h(float* __restrict__ out)
{
    extern __shared__ __half smh[];
    const size_t m0 = (size_t)blockIdx.y << 7;
    const size_t n0 = (size_t)blockIdx.x << 8;

    float acc[4][8][4];
    #pragma unroll
    for (int i = 0; i < 4; i++)
        #pragma unroll
        for (int j = 0; j < 8; j++)
            #pragma unroll
            for (int r = 0; r < 4; r++) acc[i][j][r] = 0.f;

    gemm16_acc(smem_u32(smh), g_ao16 + m0 * 2048, g_wo16 + n0 * 2048, acc);

    const int tid = threadIdx.x, wid = tid >> 5, lane = tid & 31;
    const int wm = wid >> 2, wn = wid & 3, lr = lane >> 2, lc = lane & 3;
    float* C = out + m0 * 2048 + n0;
    #pragma unroll
    for (int mi = 0; mi < 4; mi++) {
        const int row = wm * 64 + mi * 16 + lr;
        #pragma unroll
        for (int nj = 0; nj < 8; nj++) {
            const int col = wn * 64 + nj * 8 + lc * 2;
            float2 v0 = { acc[mi][nj][0], acc[mi][nj][1] };
            float2 v1 = { acc[mi][nj][2], acc[mi][nj][3] };
            *(float2*)(C + (size_t)row * 2048 + col)     = v0;
            *(float2*)(C + (size_t)(row+8) * 2048 + col) = v1;
        }
    }
}

// ---------------------------------------------------------------------------
// q/k/v build (fp16 mma, K=64) + RoPE + scatter. grid (32,32).
// V written d-major packed via register transpose (shfl + byte_perm).
// ---------------------------------------------------------------------------
#define QATS 72
#define BPS  136
#define QKV_SMEM (128*QATS*2 + 32*BPS*4)
#define SC2_ 0.12752450221065472f   // (1/sqrt(128)) * log2(e)

__global__ void __launch_bounds__(256, 1) qkv_h(
    const float* __restrict__ Bq, const float* __restrict__ Bk, const float* __restrict__ Bv,
    const float* __restrict__ fcos, const float* __restrict__ fsin,
    const int* __restrict__ widx)
{
    extern __shared__ __align__(16) char smraw[];
    __half*   As = (__half*)smraw;
    uint32_t* Bp = (uint32_t*)(smraw + 128*QATS*2);

    const int tid = threadIdx.x, w = tid >> 5, lane = tid & 31;
    const int lr = lane >> 2, lc = lane & 3;
    const int m0 = blockIdx.x << 7;
    const int hh = blockIdx.y;

    const float* Bmat; int aoff;
    if (hh < 16)      { Bmat = Bq + (size_t)hh * 8192;        aoff = hh * 64; }
    else if (hh < 24) { Bmat = Bk + (size_t)(hh - 16) * 8192; aoff = 1024 + (hh - 16) * 64; }
    else              { Bmat = Bv + (size_t)(hh - 24) * 8192; aoff = 1536 + (hh - 24) * 64; }

    #pragma unroll
    for (int i = 0; i < 4; i++) {
        int idx = tid + (i << 8);
        int r = idx >> 3, g = idx & 7;
        *(uint4*)(As + r * QATS + g * 8) =
            *(const uint4*)(g_A + (size_t)(m0 + r) * 2048 + aoff + g * 8);
    }
    #pragma unroll
    for (int i = 0; i < 4; i++) {
        int idx = tid + (i << 8);
        int r2 = idx >> 5, cg = idx & 31;
        float4 a = *(const float4*)(Bmat + (size_t)(2*r2) * 128 + cg * 4);
        float4 b = *(const float4*)(Bmat + (size_t)(2*r2+1) * 128 + cg * 4);
        uint4 o = { h2rn(a.x,b.x), h2rn(a.y,b.y), h2rn(a.z,b.z), h2rn(a.w,b.w) };
        *(uint4*)(Bp + r2 * BPS + cg * 4) = o;
    }
    __syncthreads();

    float acc[16][4];
    #pragma unroll
    for (int i = 0; i < 16; i++)
        #pragma unroll
        for (int j = 0; j < 4; j++) acc[i][j] = 0.f;

    #pragma unroll
    for (int s = 0; s < 4; s++) {
        const __half* pa = As + (w * 16 + lr) * QATS + s * 16 + 2 * lc;
        uint32_t af[4] = { *(const uint32_t*)(pa), *(const uint32_t*)(pa + 8*QATS),
                           *(const uint32_t*)(pa + 8), *(const uint32_t*)(pa + 8*QATS + 8) };
        #pragma unroll
        for (int nd = 0; nd < 16; nd++) {
            const uint32_t* pb = Bp + (s * 8 + lc) * BPS + nd * 8 + lr;
            uint32_t bf[2] = { pb[0], pb[4 * BPS] };
            mma_f16(acc[nd], af, bf);
        }
    }

    const int r0 = m0 + w * 16 + lr, r1 = r0 + 8;
    const int b  = r0 >> 11;
    const int s0 = r0 & 2047, s1 = s0 + 8;

    if (hh < 16) {
        #pragma unroll
        for (int i = 0; i < 16; i++)
            #pragma unroll
            for (int j = 0; j < 4; j++) acc[i][j] *= SC2_;
        __half* o0 = g_q + ((size_t)(b * H_ + hh) * S_ + s0) * D_;
        __half* o1 = g_q + ((size_t)(b * H_ + hh) * S_ + s1) * D_;
        #pragma unroll
        for (int nd = 0; nd < 8; nd++) {
            const int d0 = (nd << 3) + 2 * lc;
            float2 c0 = *(const float2*)(fcos + (size_t)s0*64 + d0);
            float2 z0 = *(const float2*)(fsin + (size_t)s0*64 + d0);
            float2 c1 = *(const float2*)(fcos + (size_t)s1*64 + d0);
            float2 z1 = *(const float2*)(fsin + (size_t)s1*64 + d0);
            *(uint32_t*)(o0+d0)    = h2rn(acc[nd][0]*c0.x - acc[nd+8][0]*z0.x,
                                          acc[nd][1]*c0.y - acc[nd+8][1]*z0.y);
            *(uint32_t*)(o0+d0+64) = h2rn(acc[nd][0]*z0.x + acc[nd+8][0]*c0.x,
                                          acc[nd][1]*z0.y + acc[nd+8][1]*c0.y);
            *(uint32_t*)(o1+d0)    = h2rn(acc[nd][2]*c1.x - acc[nd+8][2]*z1.x,
                                          acc[nd][3]*c1.y - acc[nd+8][3]*z1.y);
            *(uint32_t*)(o1+d0+64) = h2rn(acc[nd][2]*z1.x + acc[nd+8][2]*c1.x,
                                          acc[nd][3]*z1.y + acc[nd+8][3]*c1.y);
        }
    } else if (hh < 24) {
        int p0 = widx[s0], p1 = widx[s1];
        __half* o0 = g_k + ((size_t)(b * HKV_ + hh-16) * S_ + p0) * D_;
        __half* o1 = g_k + ((size_t)(b * HKV_ + hh-16) * S_ + p1) * D_;
        #pragma unroll
        for (int nd = 0; nd < 8; nd++) {
            const int d0 = (nd << 3) + 2 * lc;
            float2 c0 = *(const float2*)(fcos + (size_t)p0*64 + d0);
            float2 z0 = *(const float2*)(fsin + (size_t)p0*64 + d0);
            float2 c1 = *(const float2*)(fcos + (size_t)p1*64 + d0);
            float2 z1 = *(const float2*)(fsin + (size_t)p1*64 + d0);
            *(uint32_t*)(o0+d0)    = h2rn(acc[nd][0]*c0.x - acc[nd+8][0]*z0.x,
                                          acc[nd][1]*c0.y - acc[nd+8][1]*z0.y);
            *(uint32_t*)(o0+d0+64) = h2rn(acc[nd][0]*z0.x + acc[nd+8][0]*c0.x,
                                          acc[nd][1]*z0.y + acc[nd+8][1]*c0.y);
            *(uint32_t*)(o1+d0)    = h2rn(acc[nd][2]*c1.x - acc[nd+8][2]*z1.x,
                                          acc[nd][3]*c1.y - acc[nd+8][3]*z1.y);
            *(uint32_t*)(o1+d0+64) = h2rn(acc[nd][2]*z1.x + acc[nd+8][2]*c1.x,
                                          acc[nd][3]*z1.y + acc[nd+8][3]*c1.y);
        }
    } else {   // V: register transpose -> d-major packed g_v
        const int par = lr & 1;
        int pe0 = widx[s0 - par] >> 1;
        int pe1 = widx[s0 - par + 8] >> 1;
        uint32_t* gvt = (uint32_t*)g_v + (size_t)(b * HKV_ + hh - 24) * (D_ * (S_/2));
        #pragma unroll
        for (int nd = 0; nd < 16; nd++) {
            uint32_t v0 = h2rn(acc[nd][0], acc[nd][1]);
            uint32_t v1 = h2rn(acc[nd][2], acc[nd][3]);
            uint32_t q0 = __shfl_xor_sync(0xffffffffu, v0, 4);
            uint32_t q1 = __shfl_xor_sync(0xffffffffu, v1, 4);
            uint32_t o0 = par ? __byte_perm(v0, q0, 0x3276) : __byte_perm(v0, q0, 0x5410);
            uint32_t o1 = par ? __byte_perm(v1, q1, 0x3276) : __byte_perm(v1, q1, 0x5410);
            const int d = (nd << 3) + 2 * lc + par;
            gvt[(size_t)d * (S_/2) + pe0] = o0;
            gvt[(size_t)d * (S_/2) + pe1] = o1;
        }
    }
}

// ---------------------------------------------------------------------------
// Flash attention: 128x128 tiles, fp16 mma, cp.async double buffer,
// d-major V (ldsm4 PV frags), tensor-core row sums, f16x2 exp.
// ---------------------------------------------------------------------------
#define KTS 136
#define VTS 68
#define FL_BUF 71808
#define FL_SMEM (2*FL_BUF)

__device__ __forceinline__ void fl_issue(uint32_t sb, int buf,
    const __half* __restrict__ kp, const uint32_t* __restrict__ vt, int kt, int tid)
{
    uint32_t kb = sb + buf * FL_BUF;
    uint32_t vb = kb + 34816u;
    #pragma unroll
    for (int i = 0; i < 8; i++) {
        int idx = tid + (i << 8);
        int r = idx >> 4, g = idx & 15;
        cp16(kb + (r * KTS + g * 8) * 2, kp + (size_t)r * 128 + g * 8);
    }
    #pragma unroll
    for (int i = 0; i < 8; i++) {
        int idx = tid + (i << 8);
        int d = idx >> 4, g = idx & 15;
        cp16(vb + (d * VTS + g * 4) * 4, vt + (size_t)d * (S_/2) + kt * 64 + g * 4);
    }
}

__global__ void __launch_bounds__(256, 1) flash_h()
{
    extern __shared__ __align__(16) char smraw[];
    const uint32_t sb = smem_u32(smraw);

    const int tid = threadIdx.x, w = tid >> 5, lane = tid & 31;
    const int lr = lane >> 2, lc = lane & 3;
    const int arow = (lane & 7) + ((lane >> 3) & 1) * 8, acol = (lane >> 4) * 8;
    const int brow = (lane & 7) + (lane >> 4) * 8,       bcol = ((lane >> 3) & 1) * 8;
    const int vrow = ((lane >> 4) << 3) + (lane & 7),    vc4  = ((lane >> 3) & 1) * 4;
    const int qt = (int)gridDim.x - 1 - (int)blockIdx.x;
    const int bh = blockIdx.y;
    const int b = bh >> 4, h = bh & 15, kvh = h >> 1;
    const int qp = qt << 7;

    const __half*   qbase = g_q + ((size_t)(b * H_ + h) * S_ + qp) * D_;
    const __half*   kbase = g_k + (size_t)(b * HKV_ + kvh) * S_ * D_;
    const uint32_t* vtb_g = (const uint32_t*)g_v + (size_t)(b * HKV_ + kvh) * (D_ * (S_/2));

    __half* Qst = (__half*)smraw;
    #pragma unroll
    for (int i = 0; i < 8; i++) {
        int idx = tid + (i << 8);
        int r = idx >> 4, g = idx & 15;
        *(uint4*)(Qst + r * KTS + g * 8) = *(const uint4*)(qbase + (size_t)r * 128 + g * 8);
    }
    __syncthreads();
    uint32_t qf[8][4];
    #pragma unroll
    for (int k8 = 0; k8 < 8; k8++)
        ldsm4(qf[k8], sb + ((w * 16 + arow) * KTS + (k8 << 4) + acol) * 2);

    {
        uint32_t* v0 = (uint32_t*)(smraw + 34816);
        uint32_t* v1 = (uint32_t*)(smraw + FL_BUF + 34816);
        for (int i = tid; i < 512; i += 256) {
            int r = i >> 6, c = i & 63;
            v0[(128 + r) * VTS + c] = 0x3C003C00u;
            v1[(128 + r) * VTS + c] = 0x3C003C00u;
        }
    }
    __syncthreads();

    float oacc[17][4];
    #pragma unroll
    for (int i = 0; i < 17; i++)
        #pragma unroll
        for (int j = 0; j < 4; j++) oacc[i][j] = 0.f;
    float m0 = -1e30f, m1 = -1e30f;
    const int r0g = qp + w * 16 + lr, r1g = r0g + 8;

    fl_issue(sb, 0, kbase, vtb_g, 0, tid);
    CP_COMMIT();

    for (int kt = 0; kt <= qt; kt++) {
        asm volatile("cp.async.wait_group 0;");
        __syncthreads();
        if (kt < qt) {
            fl_issue(sb, (kt + 1) & 1, kbase + (size_t)(kt + 1) * 16384,
                     vtb_g, kt + 1, tid);
            CP_COMMIT();
        }

        const uint32_t kb  = sb + (kt & 1) * FL_BUF;
        const uint32_t vtb = kb + 34816u;
        const uint32_t* Vt = (const uint32_t*)(smraw + (kt & 1) * FL_BUF + 34816);

        float sacc[16][4];
        #pragma unroll
        for (int i = 0; i < 16; i++)
            #pragma unroll
            for (int j = 0; j < 4; j++) sacc[i][j] = 0.f;
        #pragma unroll
        for (int k8 = 0; k8 < 8; k8++) {
            #pragma unroll
            for (int ntp = 0; ntp < 8; ntp++) {
                uint32_t bq[4];
                ldsm4(bq, kb + ((ntp * 16 + brow) * KTS + (k8 << 4) + bcol) * 2);
                mma_f16(sacc[2*ntp],     qf[k8], bq);
                mma_f16(sacc[2*ntp + 1], qf[k8], bq + 2);
            }
        }

        if (kt == qt) {
            const int cb = kt << 7;
            #pragma unroll
            for (int nt = 0; nt < 16; nt++) {
                int c0 = cb + nt * 8 + 2 * lc;
                if (c0     > r0g) sacc[nt][0] = -1e30f;
                if (c0 + 1 > r0g) sacc[nt][1] = -1e30f;
                if (c0     > r1g) sacc[nt][2] = -1e30f;
                if (c0 + 1 > r1g) sacc[nt][3] = -1e30f;
            }
        }

        float mi0 = -1e30f, mi1 = -1e30f;
        #pragma unroll
        for (int nt = 0; nt < 16; nt++) {
            mi0 = fmaxf(mi0, fmaxf(sacc[nt][0], sacc[nt][1]));
            mi1 = fmaxf(mi1, fmaxf(sacc[nt][2], sacc[nt][3]));
        }
        mi0 = fmaxf(mi0, __shfl_xor_sync(0xffffffffu, mi0, 1));
        mi0 = fmaxf(mi0, __shfl_xor_sync(0xffffffffu, mi0, 2));
        mi1 = fmaxf(mi1, __shfl_xor_sync(0xffffffffu, mi1, 1));
        mi1 = fmaxf(mi1, __shfl_xor_sync(0xffffffffu, mi1, 2));
        float mn0 = fmaxf(m0, mi0), mn1 = fmaxf(m1, mi1);
        float sf0 = ex2(m0 - mn0), sf1 = ex2(m1 - mn1);
        m0 = mn0; m1 = mn1;

        uint32_t pf[16][2];
        #pragma unroll
        for (int nt = 0; nt < 16; nt++) {
            pf[nt][0] = hex2(sacc[nt][0] - m0, sacc[nt][1] - m0);
            pf[nt][1] = hex2(sacc[nt][2] - m1, sacc[nt][3] - m1);
        }

        #pragma unroll
        for (int nd = 0; nd < 17; nd++) {
            oacc[nd][0] *= sf0; oacc[nd][1] *= sf0;
            oacc[nd][2] *= sf1; oacc[nd][3] *= sf1;
        }

        #pragma unroll
        for (int ks = 0; ks < 8; ks++) {
            uint32_t af[4] = { pf[2*ks][0], pf[2*ks][1], pf[2*ks+1][0], pf[2*ks+1][1] };
            #pragma unroll
            for (int ndp = 0; ndp < 8; ndp++) {
                uint32_t bv[4];
                ldsm4(bv, vtb + ((ndp * 16 + vrow) * VTS + ks * 8 + vc4) * 4);
                mma_f16(oacc[2*ndp],     af, bv);
                mma_f16(oacc[2*ndp + 1], af, bv + 2);
            }
            const uint32_t* po = Vt + (128 + lr) * VTS + ks * 8 + lc;
            uint32_t bo[2] = { po[0], po[4] };
            mma_f16(oacc[16], af, bo);
        }
        __syncthreads();
    }

    float i0 = 1.f / oacc[16][0], i1 = 1.f / oacc[16][2];
    __half* o0 = g_ao16 + ((size_t)b * S_ + r0g) * 2048 + h * 128 + 2 * lc;
    __half* o1 = g_ao16 + ((size_t)b * S_ + r1g) * 2048 + h * 128 + 2 * lc;
    #pragma unroll
    for (int nd = 0; nd < 16; nd++) {
        *(uint32_t*)(o0 + nd * 8) = h2rn(oacc[nd][0] * i0, oacc[nd][1] * i0);
        *(uint32_t*)(o1 + nd * 8) = h2rn(oacc[nd][2] * i1, oacc[nd][3] * i1);
    }
}

// ---------------------------------------------------------------------------
extern "C" void kernel_launch(void* const* d_in, const int* in_sizes, int n_in,
                              void* d_out, int out_size)
{
    const float* hs   = (const float*)d_in[0];
    const float* WAq  = (const float*)d_in[1];
    const float* WAk  = (const float*)d_in[2];
    const float* WAv  = (const float*)d_in[3];
    const float* Bq   = (const float*)d_in[4];
    const float* Bk   = (const float*)d_in[5];
    const float* Bv   = (const float*)d_in[6];
    const float* Wo   = (const float*)d_in[7];
    const float* fcos = (const float*)d_in[8];
    const float* fsin = (const float*)d_in[9];
    const int*   widx = (const int*)d_in[11];
    float* out = (float*)d_out;

    cudaFuncSetAttribute(proj_h,  cudaFuncAttributeMaxDynamicSharedMemorySize, G16_SMEM);
    cudaFuncSetAttribute(oproj_h, cudaFuncAttributeMaxDynamicSharedMemorySize, G16_SMEM);
    cudaFuncSetAttribute(qkv_h,   cudaFuncAttributeMaxDynamicSharedMemorySize, QKV_SMEM);
    cudaFuncSetAttribute(flash_h, cudaFuncAttributeMaxDynamicSharedMemorySize, FL_SMEM);

    cvt_all<<<8192, 256>>>(hs, WAq, WAk, WAv, Wo);
    proj_h <<<dim3(8, 32), 256, G16_SMEM>>>();
    qkv_h  <<<dim3(32, 32), 256, QKV_SMEM>>>(Bq, Bk, Bv, fcos, fsin, widx);
    flash_h<<<dim3(S_ / 128, B_ * H_), 256, FL_SMEM>>>();
    oproj_h<<<dim3(8, 32), 256, G16_SMEM>>>(out);
}